// round 1
// baseline (speedup 1.0000x reference)
#include <cuda_runtime.h>

#define NN 50000
#define DH 128
#define GG 64
#define EPSF 1e-5f
#define EMAX 800000
#define ETOTMAX (EMAX + NN)

// ---------------- scratch (static device globals; no allocations) ----------------
__device__ float g_h[NN * DH];      // h = X @ W (current layer)
__device__ float g_x2[NN * DH];     // aggregated + post-processed node features
__device__ float g_als[NN];
__device__ float g_ald[NN];
__device__ int   g_deg[NN];
__device__ int   g_cur[NN];
__device__ int   g_off[NN + 1];
__device__ int   g_csrc[ETOTMAX];
__device__ int   g_is64;
__device__ int   g_start[GG + 1];
__device__ float g_pool[GG * DH];
__device__ float g_logits[GG * DH];

__device__ __forceinline__ int idx_at(const void* p, long long i, int is64) {
    if (is64) return (int)((const long long*)p)[i];
    return ((const int*)p)[i];
}

// ---------------- dtype detection (int64 vs int32 edge/batch arrays) ----------------
__global__ void k_detect(const int* ei32) {
    // int64 little-endian: every odd 32-bit word is 0 (values < 50000).
    // int32 random values: essentially impossible for 2048 samples to all be 0.
    int flag = 1;
    for (int k = 0; k < 2048; k++) {
        if (ei32[2 * k + 1] != 0) { flag = 0; break; }
    }
    g_is64 = flag;
}

__global__ void k_zero() {
    for (int i = blockIdx.x * blockDim.x + threadIdx.x; i < NN;
         i += gridDim.x * blockDim.x) {
        g_deg[i] = 0;
        g_cur[i] = 0;
    }
}

// ---------------- CSR build: histogram -> scan -> scatter ----------------
__global__ void k_hist(const void* ei, int E) {
    int is64 = g_is64;
    int tot = E + NN;
    for (int i = blockIdx.x * blockDim.x + threadIdx.x; i < tot;
         i += gridDim.x * blockDim.x) {
        int dst = (i < E) ? idx_at(ei, (long long)E + i, is64) : (i - E);
        atomicAdd(&g_deg[dst], 1);
    }
}

__global__ void k_scan() {
    __shared__ int ss[1024];
    int tid = threadIdx.x;
    const int CH = (NN + 1023) / 1024;  // 49
    int base = tid * CH;
    int s = 0;
    for (int i = 0; i < CH; i++) {
        int id = base + i;
        if (id < NN) s += g_deg[id];
    }
    ss[tid] = s;
    __syncthreads();
    for (int o = 1; o < 1024; o <<= 1) {
        int v = (tid >= o) ? ss[tid - o] : 0;
        __syncthreads();
        ss[tid] += v;
        __syncthreads();
    }
    int run = (tid > 0) ? ss[tid - 1] : 0;
    for (int i = 0; i < CH; i++) {
        int id = base + i;
        if (id < NN) {
            g_off[id] = run;
            run += g_deg[id];
        }
    }
    if (tid == 1023) g_off[NN] = ss[1023];
}

__global__ void k_scatter(const void* ei, int E) {
    int is64 = g_is64;
    int tot = E + NN;
    for (int i = blockIdx.x * blockDim.x + threadIdx.x; i < tot;
         i += gridDim.x * blockDim.x) {
        int src, dst;
        if (i < E) {
            src = idx_at(ei, i, is64);
            dst = idx_at(ei, (long long)E + i, is64);
        } else {
            src = i - E;
            dst = i - E;
        }
        int p = atomicAdd(&g_cur[dst], 1);
        g_csrc[g_off[dst] + p] = src;
    }
}

// ---------------- GEMM (h = X@W) fused with attention logits als/ald ----------------
// 256 threads, 64-row x 128-col tile, 8x4 register tile per thread.
__global__ void __launch_bounds__(256) k_gemm(const float* __restrict__ Xext,
                                              int use_internal,
                                              const float* __restrict__ W,
                                              const float* __restrict__ asrc,
                                              const float* __restrict__ adst) {
    __shared__ float Xs[64][36];   // padded: conflict-free float4 stores
    __shared__ float Ws[32][128];
    const float* X = use_internal ? g_x2 : Xext;
    int t = threadIdx.x;
    int tx = t & 31, ty = t >> 5;
    int rowBase = blockIdx.x * 64;

    float acc[8][4];
#pragma unroll
    for (int j = 0; j < 8; j++)
#pragma unroll
        for (int q = 0; q < 4; q++) acc[j][q] = 0.f;

    for (int kb = 0; kb < DH; kb += 32) {
        // Load X tile: 64 rows x 32 cols = 512 float4; 2 per thread
#pragma unroll
        for (int i = 0; i < 2; i++) {
            int f = t + i * 256;
            int r = f >> 3, kk4 = f & 7;
            int row = rowBase + r;
            float4 v = make_float4(0.f, 0.f, 0.f, 0.f);
            if (row < NN) v = *(const float4*)&X[row * DH + kb + kk4 * 4];
            *(float4*)&Xs[r][kk4 * 4] = v;
        }
        // Load W tile: 32 rows x 128 cols = 1024 float4; 4 per thread
#pragma unroll
        for (int i = 0; i < 4; i++) {
            int f = t + i * 256;
            int kr = f >> 5, c4 = f & 31;
            *(float4*)&Ws[kr][c4 * 4] = *(const float4*)&W[(kb + kr) * DH + c4 * 4];
        }
        __syncthreads();
#pragma unroll
        for (int kk = 0; kk < 32; kk++) {
            float4 wv = *(float4*)&Ws[kk][tx * 4];
#pragma unroll
            for (int j = 0; j < 8; j++) {
                float xv = Xs[ty * 8 + j][kk];  // warp broadcast
                acc[j][0] += xv * wv.x;
                acc[j][1] += xv * wv.y;
                acc[j][2] += xv * wv.z;
                acc[j][3] += xv * wv.w;
            }
        }
        __syncthreads();
    }

    float4 as4 = *(const float4*)&asrc[tx * 4];
    float4 ad4 = *(const float4*)&adst[tx * 4];
#pragma unroll
    for (int j = 0; j < 8; j++) {
        int row = rowBase + ty * 8 + j;
        if (row < NN) {
            *(float4*)&g_h[row * DH + tx * 4] =
                make_float4(acc[j][0], acc[j][1], acc[j][2], acc[j][3]);
        }
        float ps = acc[j][0] * as4.x + acc[j][1] * as4.y + acc[j][2] * as4.z +
                   acc[j][3] * as4.w;
        float pd = acc[j][0] * ad4.x + acc[j][1] * ad4.y + acc[j][2] * ad4.z +
                   acc[j][3] * ad4.w;
#pragma unroll
        for (int o = 16; o > 0; o >>= 1) {
            ps += __shfl_xor_sync(0xffffffffu, ps, o);
            pd += __shfl_xor_sync(0xffffffffu, pd, o);
        }
        if (tx == 0 && row < NN) {
            g_als[row] = ps;
            g_ald[row] = pd;
        }
    }
}

// ---------------- warp-per-node aggregation + fused epilogue ----------------
// out[v] = sum_j exp(lrelu(als[src_j]+ald[v])) * h[src_j] / sum_j exp(...)
// MODE 1: +bias, relu, layernorm         (layer 1)
// MODE 2: +bias, layernorm, relu         (layer 2)
template <int MODE>
__global__ void __launch_bounds__(256) k_agg(const float* __restrict__ bias,
                                             const float* __restrict__ lng,
                                             const float* __restrict__ lnb) {
    int w = (blockIdx.x * blockDim.x + threadIdx.x) >> 5;
    int lane = threadIdx.x & 31;
    if (w >= NN) return;
    int js = g_off[w], je = g_off[w + 1];
    float aldv = g_ald[w];
    float ax = 0.f, ay = 0.f, az = 0.f, aw = 0.f, z = 0.f;

    // software pipeline the src-index + als lookups one iteration ahead
    int s_n = g_csrc[js];
    float als_n = g_als[s_n];
    for (int j = js; j < je; j++) {
        int s = s_n;
        float alsv = als_n;
        if (j + 1 < je) {
            s_n = g_csrc[j + 1];
            als_n = g_als[s_n];
        }
        float4 hv = *(const float4*)&g_h[s * DH + lane * 4];
        float a = alsv + aldv;
        a = a > 0.f ? a : 0.2f * a;
        float e = __expf(a);
        ax += e * hv.x;
        ay += e * hv.y;
        az += e * hv.z;
        aw += e * hv.w;
        z += e;
    }
    float inv = 1.f / z;
    float4 b4 = *(const float4*)&bias[lane * 4];
    float c0 = ax * inv + b4.x;
    float c1 = ay * inv + b4.y;
    float c2 = az * inv + b4.z;
    float c3 = aw * inv + b4.w;
    if (MODE == 1) {
        c0 = fmaxf(c0, 0.f);
        c1 = fmaxf(c1, 0.f);
        c2 = fmaxf(c2, 0.f);
        c3 = fmaxf(c3, 0.f);
    }
    // layernorm over 128 (warp allreduce)
    float tot = c0 + c1 + c2 + c3;
#pragma unroll
    for (int o = 16; o > 0; o >>= 1) tot += __shfl_xor_sync(0xffffffffu, tot, o);
    float mu = tot * (1.f / DH);
    float d0 = c0 - mu, d1 = c1 - mu, d2 = c2 - mu, d3 = c3 - mu;
    float ssq = d0 * d0 + d1 * d1 + d2 * d2 + d3 * d3;
#pragma unroll
    for (int o = 16; o > 0; o >>= 1) ssq += __shfl_xor_sync(0xffffffffu, ssq, o);
    float var = ssq * (1.f / DH);
    float sc = rsqrtf(var + EPSF);
    float4 g4 = *(const float4*)&lng[lane * 4];
    float4 bb = *(const float4*)&lnb[lane * 4];
    float o0 = d0 * sc * g4.x + bb.x;
    float o1 = d1 * sc * g4.y + bb.y;
    float o2 = d2 * sc * g4.z + bb.z;
    float o3 = d3 * sc * g4.w + bb.w;
    if (MODE == 2) {
        o0 = fmaxf(o0, 0.f);
        o1 = fmaxf(o1, 0.f);
        o2 = fmaxf(o2, 0.f);
        o3 = fmaxf(o3, 0.f);
    }
    *(float4*)&g_x2[w * DH + lane * 4] = make_float4(o0, o1, o2, o3);
}

// ---------------- pooling (batch is sorted -> segment boundaries via bsearch) ----------------
__global__ void k_bounds(const void* batch) {
    int g = threadIdx.x;
    if (g > GG) return;
    int is64 = g_is64;
    int lo = 0, hi = NN;
    while (lo < hi) {
        int m = (lo + hi) >> 1;
        if (idx_at(batch, m, is64) < g) lo = m + 1;
        else hi = m;
    }
    g_start[g] = lo;
}

__global__ void k_pool() {
    int g = blockIdx.x, c = threadIdx.x;
    int s = g_start[g], e = g_start[g + 1];
    float sum = 0.f;
    for (int r = s; r < e; r++) sum += g_x2[r * DH + c];
    int cnt = e - s;
    g_pool[g * DH + c] = sum / (float)max(cnt, 1);
}

__global__ void k_fc(const float* __restrict__ fcW, const float* __restrict__ fcb) {
    __shared__ float pr[DH];
    int g = blockIdx.x, o = threadIdx.x;
    pr[o] = g_pool[g * DH + o];
    __syncthreads();
    float acc = fcb[o];
#pragma unroll 4
    for (int k = 0; k < DH; k++) acc += pr[k] * fcW[k * DH + o];
    g_logits[g * DH + o] = acc;
}

__global__ void k_bn(const float* __restrict__ bng, const float* __restrict__ bnb,
                     float* __restrict__ out) {
    int o = threadIdx.x;
    float mu = 0.f;
    for (int g = 0; g < GG; g++) mu += g_logits[g * DH + o];
    mu *= (1.f / GG);
    float var = 0.f;
    for (int g = 0; g < GG; g++) {
        float d = g_logits[g * DH + o] - mu;
        var += d * d;
    }
    var *= (1.f / GG);
    float sc = rsqrtf(var + EPSF);
    float gg = bng[o], bb = bnb[o];
    for (int g = 0; g < GG; g++)
        out[g * DH + o] = (g_logits[g * DH + o] - mu) * sc * gg + bb;
}

// ---------------- launch ----------------
extern "C" void kernel_launch(void* const* d_in, const int* in_sizes, int n_in,
                              void* d_out, int out_size) {
    const float* x    = (const float*)d_in[0];
    const void*  ei   = d_in[1];
    const void*  bat  = d_in[2];
    const float* W1   = (const float*)d_in[3];
    const float* as1  = (const float*)d_in[4];
    const float* ad1  = (const float*)d_in[5];
    const float* b1   = (const float*)d_in[6];
    const float* W2   = (const float*)d_in[7];
    const float* as2  = (const float*)d_in[8];
    const float* ad2  = (const float*)d_in[9];
    const float* b2   = (const float*)d_in[10];
    const float* ln1g = (const float*)d_in[11];
    const float* ln1b = (const float*)d_in[12];
    const float* ln2g = (const float*)d_in[13];
    const float* ln2b = (const float*)d_in[14];
    const float* fcW  = (const float*)d_in[15];
    const float* fcb  = (const float*)d_in[16];
    const float* bng  = (const float*)d_in[17];
    const float* bnb  = (const float*)d_in[18];
    float* out = (float*)d_out;
    int E = in_sizes[1] / 2;

    // CSR build (shared by both layers)
    k_detect<<<1, 1>>>((const int*)ei);
    k_zero<<<98, 512>>>();
    k_hist<<<512, 256>>>(ei, E);
    k_scan<<<1, 1024>>>();
    k_scatter<<<512, 256>>>(ei, E);

    // layer 1
    k_gemm<<<(NN + 63) / 64, 256>>>(x, 0, W1, as1, ad1);
    k_agg<1><<<NN / 8, 256>>>(b1, ln1g, ln1b);

    // layer 2
    k_gemm<<<(NN + 63) / 64, 256>>>(nullptr, 1, W2, as2, ad2);
    k_agg<2><<<NN / 8, 256>>>(b2, ln2g, ln2b);

    // pool + fc + bn
    k_bounds<<<1, 128>>>(bat);
    k_pool<<<GG, 128>>>();
    k_fc<<<GG, 128>>>(fcW, fcb);
    k_bn<<<1, 128>>>(bng, bnb, out);
}

// round 3
// speedup vs baseline: 1.1713x; 1.1713x over previous
#include <cuda_runtime.h>

#define NN 50000
#define DH 128
#define GG 64
#define EPSF 1e-5f
#define EMAX 800000
#define ETOTMAX (EMAX + NN)
#define SCAN_B 256          // elems per scan block
#define SCAN_NB ((NN + SCAN_B - 1) / SCAN_B)   // 196

// ---------------- scratch (static device globals; no allocations) ----------------
__device__ float g_h[NN * DH];
__device__ float g_x2[NN * DH];
__device__ float g_als[NN];
__device__ float g_ald[NN];
__device__ int   g_deg[NN];
__device__ int   g_cur[NN];
__device__ int   g_off[NN + 1];
__device__ int   g_csrc[ETOTMAX];
__device__ int   g_is64;
__device__ int   g_bsum[SCAN_NB];
__device__ int   g_boff[SCAN_NB];
__device__ int   g_start[GG + 1];
__device__ float g_pool[GG * DH];
__device__ float g_logits[GG * DH];

__device__ __forceinline__ int idx_at(const void* p, long long i, int is64) {
    if (is64) return (int)((const long long*)p)[i];
    return ((const int*)p)[i];
}

// ---------------- dtype detection (int64 vs int32), parallel ----------------
__global__ void k_detect(const int* ei32) {
    __shared__ int bad;
    if (threadIdx.x == 0) bad = 0;
    __syncthreads();
    int t = threadIdx.x;
    int any = 0;
#pragma unroll
    for (int i = 0; i < 8; i++) {
        if (ei32[2 * (t * 8 + i) + 1] != 0) any = 1;
    }
    if (any) atomicOr(&bad, 1);
    __syncthreads();
    if (t == 0) g_is64 = !bad;
}

__global__ void k_zero() {
    for (int i = blockIdx.x * blockDim.x + threadIdx.x; i < NN;
         i += gridDim.x * blockDim.x) {
        g_deg[i] = 0;
        g_cur[i] = 0;
    }
}

// ---------------- CSR build: histogram -> 3-phase scan -> scatter ----------------
__global__ void k_hist(const void* ei, int E) {
    int is64 = g_is64;
    int tot = E + NN;
    for (int i = blockIdx.x * blockDim.x + threadIdx.x; i < tot;
         i += gridDim.x * blockDim.x) {
        int dst = (i < E) ? idx_at(ei, (long long)E + i, is64) : (i - E);
        atomicAdd(&g_deg[dst], 1);
    }
}

// phase 1: per-block sums
__global__ void __launch_bounds__(SCAN_B) k_scan_bsum() {
    __shared__ int ss[SCAN_B];
    int id = blockIdx.x * SCAN_B + threadIdx.x;
    int v = (id < NN) ? g_deg[id] : 0;
    ss[threadIdx.x] = v;
    __syncthreads();
    for (int o = SCAN_B / 2; o > 0; o >>= 1) {
        if (threadIdx.x < o) ss[threadIdx.x] += ss[threadIdx.x + o];
        __syncthreads();
    }
    if (threadIdx.x == 0) g_bsum[blockIdx.x] = ss[0];
}

// phase 2: scan of block sums (1 block of 256 >= 196)
__global__ void __launch_bounds__(256) k_scan_top() {
    __shared__ int ss[256];
    int t = threadIdx.x;
    int v = (t < SCAN_NB) ? g_bsum[t] : 0;
    ss[t] = v;
    __syncthreads();
    for (int o = 1; o < 256; o <<= 1) {
        int u = (t >= o) ? ss[t - o] : 0;
        __syncthreads();
        ss[t] += u;
        __syncthreads();
    }
    if (t < SCAN_NB) g_boff[t] = ss[t] - v;  // exclusive
}

// phase 3: local inclusive scan + block offset -> exclusive g_off
__global__ void __launch_bounds__(SCAN_B) k_scan_expand() {
    __shared__ int ss[SCAN_B];
    int t = threadIdx.x;
    int id = blockIdx.x * SCAN_B + t;
    int v = (id < NN) ? g_deg[id] : 0;
    ss[t] = v;
    __syncthreads();
    for (int o = 1; o < SCAN_B; o <<= 1) {
        int u = (t >= o) ? ss[t - o] : 0;
        __syncthreads();
        ss[t] += u;
        __syncthreads();
    }
    int base = g_boff[blockIdx.x];
    if (id < NN) {
        g_off[id] = base + ss[t] - v;       // exclusive
        if (id == NN - 1) g_off[NN] = base + ss[t];
    }
}

__global__ void k_scatter(const void* ei, int E) {
    int is64 = g_is64;
    int tot = E + NN;
    for (int i = blockIdx.x * blockDim.x + threadIdx.x; i < tot;
         i += gridDim.x * blockDim.x) {
        int src, dst;
        if (i < E) {
            src = idx_at(ei, i, is64);
            dst = idx_at(ei, (long long)E + i, is64);
        } else {
            src = i - E;
            dst = i - E;
        }
        int p = atomicAdd(&g_cur[dst], 1);
        g_csrc[g_off[dst] + p] = src;
    }
}

// ---------------- GEMM (h = X@W) fused with attention logits ----------------
// 256 threads, 128x128 tile, 8x8 register tile per thread, BK=32.
__global__ void __launch_bounds__(256) k_gemm(const float* __restrict__ Xext,
                                              int use_internal,
                                              const float* __restrict__ W,
                                              const float* __restrict__ asrc,
                                              const float* __restrict__ adst) {
    __shared__ float Xs[128][36];   // pad 36: 16B-aligned rows, shifted banks
    __shared__ float Ws[32][128];
    const float* X = use_internal ? g_x2 : Xext;
    int t = threadIdx.x;
    int tx = t & 15;        // col group (8 cols each)
    int ty = t >> 4;        // row group (8 rows each)
    int rowBase = blockIdx.x * 128;

    float acc[8][8];
#pragma unroll
    for (int j = 0; j < 8; j++)
#pragma unroll
        for (int q = 0; q < 8; q++) acc[j][q] = 0.f;

    for (int kb = 0; kb < DH; kb += 32) {
        // X tile: 128 rows x 32 k = 1024 float4 -> 4 per thread
#pragma unroll
        for (int i = 0; i < 4; i++) {
            int f = t + i * 256;
            int r = f >> 3, kk4 = f & 7;
            int row = rowBase + r;
            float4 v = make_float4(0.f, 0.f, 0.f, 0.f);
            if (row < NN) v = *(const float4*)&X[row * DH + kb + kk4 * 4];
            *(float4*)&Xs[r][kk4 * 4] = v;
        }
        // W tile: 32 rows x 128 cols = 1024 float4 -> 4 per thread
#pragma unroll
        for (int i = 0; i < 4; i++) {
            int f = t + i * 256;
            int kr = f >> 5, c4 = f & 31;
            *(float4*)&Ws[kr][c4 * 4] = *(const float4*)&W[(kb + kr) * DH + c4 * 4];
        }
        __syncthreads();
#pragma unroll
        for (int kk = 0; kk < 32; kk++) {
            float4 w0 = *(float4*)&Ws[kk][tx * 8];
            float4 w1 = *(float4*)&Ws[kk][tx * 8 + 4];
            float a[8];
#pragma unroll
            for (int j = 0; j < 8; j++) a[j] = Xs[ty * 8 + j][kk];
#pragma unroll
            for (int j = 0; j < 8; j++) {
                acc[j][0] += a[j] * w0.x;
                acc[j][1] += a[j] * w0.y;
                acc[j][2] += a[j] * w0.z;
                acc[j][3] += a[j] * w0.w;
                acc[j][4] += a[j] * w1.x;
                acc[j][5] += a[j] * w1.y;
                acc[j][6] += a[j] * w1.z;
                acc[j][7] += a[j] * w1.w;
            }
        }
        __syncthreads();
    }

    float4 as0 = *(const float4*)&asrc[tx * 8];
    float4 as1 = *(const float4*)&asrc[tx * 8 + 4];
    float4 ad0 = *(const float4*)&adst[tx * 8];
    float4 ad1 = *(const float4*)&adst[tx * 8 + 4];
#pragma unroll
    for (int j = 0; j < 8; j++) {
        int row = rowBase + ty * 8 + j;
        if (row < NN) {
            *(float4*)&g_h[row * DH + tx * 8] =
                make_float4(acc[j][0], acc[j][1], acc[j][2], acc[j][3]);
            *(float4*)&g_h[row * DH + tx * 8 + 4] =
                make_float4(acc[j][4], acc[j][5], acc[j][6], acc[j][7]);
        }
        float ps = acc[j][0] * as0.x + acc[j][1] * as0.y + acc[j][2] * as0.z +
                   acc[j][3] * as0.w + acc[j][4] * as1.x + acc[j][5] * as1.y +
                   acc[j][6] * as1.z + acc[j][7] * as1.w;
        float pd = acc[j][0] * ad0.x + acc[j][1] * ad0.y + acc[j][2] * ad0.z +
                   acc[j][3] * ad0.w + acc[j][4] * ad1.x + acc[j][5] * ad1.y +
                   acc[j][6] * ad1.z + acc[j][7] * ad1.w;
        // reduce across the 16 lanes of this row group (within warp halves)
#pragma unroll
        for (int o = 8; o > 0; o >>= 1) {
            ps += __shfl_xor_sync(0xffffffffu, ps, o);
            pd += __shfl_xor_sync(0xffffffffu, pd, o);
        }
        if (tx == 0 && row < NN) {
            g_als[row] = ps;
            g_ald[row] = pd;
        }
    }
}

// ---------------- warp-per-node aggregation + fused epilogue ----------------
template <int MODE>
__global__ void __launch_bounds__(256) k_agg(const float* __restrict__ bias,
                                             const float* __restrict__ lng,
                                             const float* __restrict__ lnb) {
    int w = (blockIdx.x * blockDim.x + threadIdx.x) >> 5;
    int lane = threadIdx.x & 31;
    if (w >= NN) return;
    int js = g_off[w], je = g_off[w + 1];
    float aldv = g_ald[w];
    float ax = 0.f, ay = 0.f, az = 0.f, aw = 0.f, z = 0.f;

    int s_n = g_csrc[js];
    float als_n = g_als[s_n];
    for (int j = js; j < je; j++) {
        int s = s_n;
        float alsv = als_n;
        if (j + 1 < je) {
            s_n = g_csrc[j + 1];
            als_n = g_als[s_n];
        }
        float4 hv = *(const float4*)&g_h[s * DH + lane * 4];
        float a = alsv + aldv;
        a = a > 0.f ? a : 0.2f * a;
        float e = __expf(a);
        ax += e * hv.x;
        ay += e * hv.y;
        az += e * hv.z;
        aw += e * hv.w;
        z += e;
    }
    float inv = 1.f / z;
    float4 b4 = *(const float4*)&bias[lane * 4];
    float c0 = ax * inv + b4.x;
    float c1 = ay * inv + b4.y;
    float c2 = az * inv + b4.z;
    float c3 = aw * inv + b4.w;
    if (MODE == 1) {
        c0 = fmaxf(c0, 0.f); c1 = fmaxf(c1, 0.f);
        c2 = fmaxf(c2, 0.f); c3 = fmaxf(c3, 0.f);
    }
    float tot = c0 + c1 + c2 + c3;
#pragma unroll
    for (int o = 16; o > 0; o >>= 1) tot += __shfl_xor_sync(0xffffffffu, tot, o);
    float mu = tot * (1.f / DH);
    float d0 = c0 - mu, d1 = c1 - mu, d2 = c2 - mu, d3 = c3 - mu;
    float ssq = d0 * d0 + d1 * d1 + d2 * d2 + d3 * d3;
#pragma unroll
    for (int o = 16; o > 0; o >>= 1) ssq += __shfl_xor_sync(0xffffffffu, ssq, o);
    float var = ssq * (1.f / DH);
    float sc = rsqrtf(var + EPSF);
    float4 g4 = *(const float4*)&lng[lane * 4];
    float4 bb = *(const float4*)&lnb[lane * 4];
    float o0 = d0 * sc * g4.x + bb.x;
    float o1 = d1 * sc * g4.y + bb.y;
    float o2 = d2 * sc * g4.z + bb.z;
    float o3 = d3 * sc * g4.w + bb.w;
    if (MODE == 2) {
        o0 = fmaxf(o0, 0.f); o1 = fmaxf(o1, 0.f);
        o2 = fmaxf(o2, 0.f); o3 = fmaxf(o3, 0.f);
    }
    *(float4*)&g_x2[w * DH + lane * 4] = make_float4(o0, o1, o2, o3);
}

// ---------------- pooling ----------------
__global__ void k_bounds(const void* batch) {
    int g = threadIdx.x;
    if (g > GG) return;
    int is64 = g_is64;
    int lo = 0, hi = NN;
    while (lo < hi) {
        int m = (lo + hi) >> 1;
        if (idx_at(batch, m, is64) < g) lo = m + 1;
        else hi = m;
    }
    g_start[g] = lo;
}

// 512 threads: 4 partial reducers per column, deterministic combine in shared
__global__ void __launch_bounds__(512) k_pool() {
    __shared__ float part[4][DH];
    int g = blockIdx.x;
    int c = threadIdx.x & 127;
    int q = threadIdx.x >> 7;
    int s = g_start[g], e = g_start[g + 1];
    int cnt = e - s;
    int chunk = (cnt + 3) >> 2;
    int rs = s + q * chunk;
    int re = min(rs + chunk, e);
    float sum = 0.f;
    for (int r = rs; r < re; r++) sum += g_x2[r * DH + c];
    part[q][c] = sum;
    __syncthreads();
    if (q == 0) {
        float tot = part[0][c] + part[1][c] + part[2][c] + part[3][c];
        g_pool[g * DH + c] = tot / (float)max(cnt, 1);
    }
}

__global__ void k_fc(const float* __restrict__ fcW, const float* __restrict__ fcb) {
    __shared__ float pr[DH];
    int g = blockIdx.x, o = threadIdx.x;
    pr[o] = g_pool[g * DH + o];
    __syncthreads();
    float acc = fcb[o];
#pragma unroll 4
    for (int k = 0; k < DH; k++) acc += pr[k] * fcW[k * DH + o];
    g_logits[g * DH + o] = acc;
}

__global__ void k_bn(const float* __restrict__ bng, const float* __restrict__ bnb,
                     float* __restrict__ out) {
    int o = threadIdx.x;
    float mu = 0.f;
    for (int g = 0; g < GG; g++) mu += g_logits[g * DH + o];
    mu *= (1.f / GG);
    float var = 0.f;
    for (int g = 0; g < GG; g++) {
        float d = g_logits[g * DH + o] - mu;
        var += d * d;
    }
    var *= (1.f / GG);
    float sc = rsqrtf(var + EPSF);
    float gg = bng[o], bb = bnb[o];
    for (int g = 0; g < GG; g++)
        out[g * DH + o] = (g_logits[g * DH + o] - mu) * sc * gg + bb;
}

// ---------------- launch ----------------
extern "C" void kernel_launch(void* const* d_in, const int* in_sizes, int n_in,
                              void* d_out, int out_size) {
    const float* x    = (const float*)d_in[0];
    const void*  ei   = d_in[1];
    const void*  bat  = d_in[2];
    const float* W1   = (const float*)d_in[3];
    const float* as1  = (const float*)d_in[4];
    const float* ad1  = (const float*)d_in[5];
    const float* b1   = (const float*)d_in[6];
    const float* W2   = (const float*)d_in[7];
    const float* as2  = (const float*)d_in[8];
    const float* ad2  = (const float*)d_in[9];
    const float* b2   = (const float*)d_in[10];
    const float* ln1g = (const float*)d_in[11];
    const float* ln1b = (const float*)d_in[12];
    const float* ln2g = (const float*)d_in[13];
    const float* ln2b = (const float*)d_in[14];
    const float* fcW  = (const float*)d_in[15];
    const float* fcb  = (const float*)d_in[16];
    const float* bng  = (const float*)d_in[17];
    const float* bnb  = (const float*)d_in[18];
    float* out = (float*)d_out;
    int E = in_sizes[1] / 2;

    // CSR build
    k_detect<<<1, 256>>>((const int*)ei);
    k_zero<<<98, 512>>>();
    k_hist<<<512, 256>>>(ei, E);
    k_scan_bsum<<<SCAN_NB, SCAN_B>>>();
    k_scan_top<<<1, 256>>>();
    k_scan_expand<<<SCAN_NB, SCAN_B>>>();
    k_scatter<<<512, 256>>>(ei, E);

    // layer 1
    k_gemm<<<(NN + 127) / 128, 256>>>(x, 0, W1, as1, ad1);
    k_agg<1><<<NN / 8, 256>>>(b1, ln1g, ln1b);

    // layer 2
    k_gemm<<<(NN + 127) / 128, 256>>>(nullptr, 1, W2, as2, ad2);
    k_agg<2><<<NN / 8, 256>>>(b2, ln2g, ln2b);

    // pool + fc + bn
    k_bounds<<<1, 128>>>(bat);
    k_pool<<<GG, 512>>>();
    k_fc<<<GG, 128>>>(fcW, fcb);
    k_bn<<<1, 128>>>(bng, bnb, out);
}

// round 7
// speedup vs baseline: 1.3961x; 1.1920x over previous
#include <cuda_runtime.h>
#include <cuda_bf16.h>
#include <cstdint>

#define NN 50000
#define DH 128
#define GG 64
#define EPSF 1e-5f
#define EMAX 800000
#define ETOTMAX (EMAX + NN)
#define SCAN_B 256
#define SCAN_NB ((NN + SCAN_B - 1) / SCAN_B)   // 196
#define TILES ((NN + 127) / 128)               // 391
#define LDS_STRIDE 136                         // bf16 elems per smem row (68 words % 32 == 4)

// ---------------- scratch (static device globals; no allocations) ----------------
__device__ float g_h[NN * DH];
__device__ float g_x2[NN * DH];
__device__ float g_als[NN];
__device__ float g_ald[NN];
__device__ int   g_deg[NN];
__device__ int   g_cur[NN];
__device__ int   g_off[NN + 1];
__device__ int   g_csrc[ETOTMAX];
__device__ int   g_is64;
__device__ int   g_bsum[SCAN_NB];
__device__ int   g_boff[SCAN_NB];
__device__ int   g_start[GG + 1];
__device__ float g_pool[GG * DH];
__device__ float g_logits[GG * DH];
// W^T split-bf16: [layer][n*128+k]
__device__ __align__(16) __nv_bfloat16 g_Bh[2][16384];
__device__ __align__(16) __nv_bfloat16 g_Bl[2][16384];

__device__ __forceinline__ int idx_at(const void* p, long long i, int is64) {
    if (is64) return (int)((const long long*)p)[i];
    return ((const int*)p)[i];
}

// ---------------- dtype detection ----------------
__global__ void k_detect(const int* ei32) {
    __shared__ int bad;
    if (threadIdx.x == 0) bad = 0;
    __syncthreads();
    int t = threadIdx.x;
    int any = 0;
#pragma unroll
    for (int i = 0; i < 8; i++)
        if (ei32[2 * (t * 8 + i) + 1] != 0) any = 1;
    if (any) atomicOr(&bad, 1);
    __syncthreads();
    if (t == 0) g_is64 = !bad;
}

__global__ void k_zero() {
    for (int i = blockIdx.x * blockDim.x + threadIdx.x; i < NN;
         i += gridDim.x * blockDim.x) {
        g_deg[i] = 0;
        g_cur[i] = 0;
    }
}

// ---------------- CSR build ----------------
__global__ void k_hist(const void* ei, int E) {
    int is64 = g_is64;
    int tot = E + NN;
    for (int i = blockIdx.x * blockDim.x + threadIdx.x; i < tot;
         i += gridDim.x * blockDim.x) {
        int dst = (i < E) ? idx_at(ei, (long long)E + i, is64) : (i - E);
        atomicAdd(&g_deg[dst], 1);
    }
}

__global__ void __launch_bounds__(SCAN_B) k_scan_bsum() {
    __shared__ int ss[SCAN_B];
    int id = blockIdx.x * SCAN_B + threadIdx.x;
    ss[threadIdx.x] = (id < NN) ? g_deg[id] : 0;
    __syncthreads();
    for (int o = SCAN_B / 2; o > 0; o >>= 1) {
        if (threadIdx.x < o) ss[threadIdx.x] += ss[threadIdx.x + o];
        __syncthreads();
    }
    if (threadIdx.x == 0) g_bsum[blockIdx.x] = ss[0];
}

__global__ void __launch_bounds__(256) k_scan_top() {
    __shared__ int ss[256];
    int t = threadIdx.x;
    int v = (t < SCAN_NB) ? g_bsum[t] : 0;
    ss[t] = v;
    __syncthreads();
    for (int o = 1; o < 256; o <<= 1) {
        int u = (t >= o) ? ss[t - o] : 0;
        __syncthreads();
        ss[t] += u;
        __syncthreads();
    }
    if (t < SCAN_NB) g_boff[t] = ss[t] - v;
}

__global__ void __launch_bounds__(SCAN_B) k_scan_expand() {
    __shared__ int ss[SCAN_B];
    int t = threadIdx.x;
    int id = blockIdx.x * SCAN_B + t;
    int v = (id < NN) ? g_deg[id] : 0;
    ss[t] = v;
    __syncthreads();
    for (int o = 1; o < SCAN_B; o <<= 1) {
        int u = (t >= o) ? ss[t - o] : 0;
        __syncthreads();
        ss[t] += u;
        __syncthreads();
    }
    int base = g_boff[blockIdx.x];
    if (id < NN) {
        g_off[id] = base + ss[t] - v;
        if (id == NN - 1) g_off[NN] = base + ss[t];
    }
}

__global__ void k_scatter(const void* ei, int E) {
    int is64 = g_is64;
    int tot = E + NN;
    for (int i = blockIdx.x * blockDim.x + threadIdx.x; i < tot;
         i += gridDim.x * blockDim.x) {
        int src, dst;
        if (i < E) {
            src = idx_at(ei, i, is64);
            dst = idx_at(ei, (long long)E + i, is64);
        } else {
            src = i - E;
            dst = i - E;
        }
        int p = atomicAdd(&g_cur[dst], 1);
        g_csrc[g_off[dst] + p] = src;
    }
}

// ---------------- W prep: fp32 W[k][n] -> split bf16 W^T[n][k] ----------------
__global__ void k_wprep(const float* __restrict__ W1, const float* __restrict__ W2) {
    int id = blockIdx.x * blockDim.x + threadIdx.x;   // 0..32767
    int layer = id >> 14;
    int e = id & 16383;
    int k = e >> 7, n = e & 127;
    const float* W = layer ? W2 : W1;
    float w = W[k * 128 + n];
    __nv_bfloat16 hi = __float2bfloat16(w);
    float rem = w - __bfloat162float(hi);
    g_Bh[layer][n * 128 + k] = hi;
    g_Bl[layer][n * 128 + k] = __float2bfloat16(rem);
}

// ---------------- mma.sync bf16 split GEMM + fused attention logits ----------------
__device__ __forceinline__ void mma16816(float d[4], const uint32_t a[4],
                                         const uint32_t b[2]) {
    asm volatile(
        "mma.sync.aligned.m16n8k16.row.col.f32.bf16.bf16.f32 "
        "{%0,%1,%2,%3}, {%4,%5,%6,%7}, {%8,%9}, {%0,%1,%2,%3};"
        : "+f"(d[0]), "+f"(d[1]), "+f"(d[2]), "+f"(d[3])
        : "r"(a[0]), "r"(a[1]), "r"(a[2]), "r"(a[3]), "r"(b[0]), "r"(b[1]));
}

__device__ __forceinline__ void mma_pass(const __nv_bfloat16* __restrict__ A,
                                         const __nv_bfloat16* __restrict__ B,
                                         int wr, int wc, int gid, int tig,
                                         float acc[2][8][4]) {
#pragma unroll
    for (int ks = 0; ks < 8; ks++) {
        int k0 = ks * 16;
        uint32_t a[2][4];
#pragma unroll
        for (int mi = 0; mi < 2; mi++) {
            const __nv_bfloat16* p = A + (wr + mi * 16 + gid) * LDS_STRIDE + k0 + tig * 2;
            a[mi][0] = *(const uint32_t*)(p);
            a[mi][1] = *(const uint32_t*)(p + 8 * LDS_STRIDE);
            a[mi][2] = *(const uint32_t*)(p + 8);
            a[mi][3] = *(const uint32_t*)(p + 8 * LDS_STRIDE + 8);
        }
        uint32_t b[8][2];
#pragma unroll
        for (int ni = 0; ni < 8; ni++) {
            const __nv_bfloat16* p = B + (wc + ni * 8 + gid) * LDS_STRIDE + k0 + tig * 2;
            b[ni][0] = *(const uint32_t*)(p);
            b[ni][1] = *(const uint32_t*)(p + 8);
        }
#pragma unroll
        for (int mi = 0; mi < 2; mi++)
#pragma unroll
            for (int ni = 0; ni < 8; ni++) mma16816(acc[mi][ni], a[mi], b[ni]);
    }
}

// smem: A[128][136] bf16, Bh[128][136], Bl[128][136], then reduce arrays
#define SM_A   0
#define SM_BH  (128 * LDS_STRIDE)
#define SM_BL  (2 * 128 * LDS_STRIDE)
#define SM_FLT (3 * 128 * LDS_STRIDE)          // bf16 elems before float region
#define HMMA_SMEM (SM_FLT * 2 + (256 + 256 + 128 + 128) * 4)

__global__ void __launch_bounds__(256, 2)
k_hmma(const float* __restrict__ Xext, int layer,
       const float* __restrict__ asrc, const float* __restrict__ adst) {
    extern __shared__ __align__(16) char sm[];
    __nv_bfloat16* As = (__nv_bfloat16*)sm;
    __nv_bfloat16* Bh = As + SM_BH;
    __nv_bfloat16* Bl = As + SM_BL;
    float* sps = (float*)(sm + SM_FLT * 2);     // [128][2]
    float* spd = sps + 256;
    float* s_as = spd + 256;
    float* s_ad = s_as + 128;

    const float* X = layer ? g_x2 : Xext;
    int tid = threadIdx.x;
    int wid = tid >> 5, lane = tid & 31;
    int gid = lane >> 2, tig = lane & 3;
    int wr = (wid & 3) * 32;
    int wc = (wid >> 2) * 64;
    int rowBase = blockIdx.x * 128;

    // B tiles: copy pre-split W^T (hi/lo), global row=256B -> smem stride 272B
    {
        const int4* gh = (const int4*)g_Bh[layer];
        const int4* gl = (const int4*)g_Bl[layer];
#pragma unroll
        for (int i = tid; i < 2048; i += 256) {
            int r = i >> 4, c = i & 15;
            *(int4*)((char*)Bh + r * (LDS_STRIDE * 2) + c * 16) = gh[i];
            *(int4*)((char*)Bl + r * (LDS_STRIDE * 2) + c * 16) = gl[i];
        }
    }
    if (tid < 128) {
        s_as[tid] = asrc[tid];
        s_ad[tid] = adst[tid];
    }
    // A hi tile
#pragma unroll
    for (int i = 0; i < 32; i++) {
        int f = tid + i * 256;
        int r = f >> 6, kp = f & 63;
        int row = rowBase + r;
        float2 v = make_float2(0.f, 0.f);
        if (row < NN) v = *(const float2*)&X[row * DH + kp * 2];
        *(__nv_bfloat162*)&As[r * LDS_STRIDE + kp * 2] =
            __halves2bfloat162(__float2bfloat16(v.x), __float2bfloat16(v.y));
    }
    __syncthreads();

    float acc[2][8][4];
#pragma unroll
    for (int mi = 0; mi < 2; mi++)
#pragma unroll
        for (int ni = 0; ni < 8; ni++)
#pragma unroll
            for (int q = 0; q < 4; q++) acc[mi][ni][q] = 0.f;

    mma_pass(As, Bh, wr, wc, gid, tig, acc);    // hi * hi
    mma_pass(As, Bl, wr, wc, gid, tig, acc);    // hi * lo
    __syncthreads();
    // A lo tile (recompute hi, take residual)
#pragma unroll
    for (int i = 0; i < 32; i++) {
        int f = tid + i * 256;
        int r = f >> 6, kp = f & 63;
        int row = rowBase + r;
        float2 v = make_float2(0.f, 0.f);
        if (row < NN) v = *(const float2*)&X[row * DH + kp * 2];
        float lx = v.x - __bfloat162float(__float2bfloat16(v.x));
        float ly = v.y - __bfloat162float(__float2bfloat16(v.y));
        *(__nv_bfloat162*)&As[r * LDS_STRIDE + kp * 2] =
            __halves2bfloat162(__float2bfloat16(lx), __float2bfloat16(ly));
    }
    __syncthreads();
    mma_pass(As, Bh, wr, wc, gid, tig, acc);    // lo * hi

    // epilogue: store h, compute als/ald partials
    float ps[4] = {0.f, 0.f, 0.f, 0.f};
    float pd[4] = {0.f, 0.f, 0.f, 0.f};
#pragma unroll
    for (int mi = 0; mi < 2; mi++) {
#pragma unroll
        for (int ni = 0; ni < 8; ni++) {
            int col = wc + ni * 8 + tig * 2;
            float a0 = s_as[col], a1 = s_as[col + 1];
            float d0 = s_ad[col], d1 = s_ad[col + 1];
            float* v = acc[mi][ni];
            ps[mi * 2 + 0] += v[0] * a0 + v[1] * a1;
            pd[mi * 2 + 0] += v[0] * d0 + v[1] * d1;
            ps[mi * 2 + 1] += v[2] * a0 + v[3] * a1;
            pd[mi * 2 + 1] += v[2] * d0 + v[3] * d1;
            int r0 = rowBase + wr + mi * 16 + gid;
            if (r0 < NN)
                *(float2*)&g_h[r0 * DH + col] = make_float2(v[0], v[1]);
            if (r0 + 8 < NN)
                *(float2*)&g_h[(r0 + 8) * DH + col] = make_float2(v[2], v[3]);
        }
    }
    // reduce over the 4 lanes (tig) sharing each row
#pragma unroll
    for (int j = 0; j < 4; j++) {
#pragma unroll
        for (int o = 1; o <= 2; o <<= 1) {
            ps[j] += __shfl_xor_sync(0xffffffffu, ps[j], o);
            pd[j] += __shfl_xor_sync(0xffffffffu, pd[j], o);
        }
    }
    if (tig == 0) {
        int ch = wid >> 2;
#pragma unroll
        for (int j = 0; j < 4; j++) {
            int rloc = wr + (j >> 1) * 16 + (j & 1) * 8 + gid;
            sps[rloc * 2 + ch] = ps[j];
            spd[rloc * 2 + ch] = pd[j];
        }
    }
    __syncthreads();
    if (tid < 128 && rowBase + tid < NN) {
        g_als[rowBase + tid] = sps[tid * 2] + sps[tid * 2 + 1];
        g_ald[rowBase + tid] = spd[tid * 2] + spd[tid * 2 + 1];
    }
}

// ---------------- warp-per-node aggregation + fused epilogue ----------------
template <int MODE>
__global__ void __launch_bounds__(256) k_agg(const float* __restrict__ bias,
                                             const float* __restrict__ lng,
                                             const float* __restrict__ lnb) {
    int w = (blockIdx.x * blockDim.x + threadIdx.x) >> 5;
    int lane = threadIdx.x & 31;
    if (w >= NN) return;
    int js = g_off[w], je = g_off[w + 1];
    float aldv = g_ald[w];
    float ax = 0.f, ay = 0.f, az = 0.f, aw = 0.f, z = 0.f;

    int s_n = g_csrc[js];
    float als_n = g_als[s_n];
    for (int j = js; j < je; j++) {
        int s = s_n;
        float alsv = als_n;
        if (j + 1 < je) {
            s_n = g_csrc[j + 1];
            als_n = g_als[s_n];
        }
        float4 hv = *(const float4*)&g_h[s * DH + lane * 4];
        float a = alsv + aldv;
        a = a > 0.f ? a : 0.2f * a;
        float e = __expf(a);
        ax += e * hv.x;
        ay += e * hv.y;
        az += e * hv.z;
        aw += e * hv.w;
        z += e;
    }
    float inv = 1.f / z;
    float4 b4 = *(const float4*)&bias[lane * 4];
    float c0 = ax * inv + b4.x;
    float c1 = ay * inv + b4.y;
    float c2 = az * inv + b4.z;
    float c3 = aw * inv + b4.w;
    if (MODE == 1) {
        c0 = fmaxf(c0, 0.f); c1 = fmaxf(c1, 0.f);
        c2 = fmaxf(c2, 0.f); c3 = fmaxf(c3, 0.f);
    }
    float tot = c0 + c1 + c2 + c3;
#pragma unroll
    for (int o = 16; o > 0; o >>= 1) tot += __shfl_xor_sync(0xffffffffu, tot, o);
    float mu = tot * (1.f / DH);
    float d0 = c0 - mu, d1 = c1 - mu, d2 = c2 - mu, d3 = c3 - mu;
    float ssq = d0 * d0 + d1 * d1 + d2 * d2 + d3 * d3;
#pragma unroll
    for (int o = 16; o > 0; o >>= 1) ssq += __shfl_xor_sync(0xffffffffu, ssq, o);
    float var = ssq * (1.f / DH);
    float sc = rsqrtf(var + EPSF);
    float4 g4 = *(const float4*)&lng[lane * 4];
    float4 bb = *(const float4*)&lnb[lane * 4];
    float o0 = d0 * sc * g4.x + bb.x;
    float o1 = d1 * sc * g4.y + bb.y;
    float o2 = d2 * sc * g4.z + bb.z;
    float o3 = d3 * sc * g4.w + bb.w;
    if (MODE == 2) {
        o0 = fmaxf(o0, 0.f); o1 = fmaxf(o1, 0.f);
        o2 = fmaxf(o2, 0.f); o3 = fmaxf(o3, 0.f);
    }
    *(float4*)&g_x2[w * DH + lane * 4] = make_float4(o0, o1, o2, o3);
}

// ---------------- pooling ----------------
__global__ void k_bounds(const void* batch) {
    int g = threadIdx.x;
    if (g > GG) return;
    int is64 = g_is64;
    int lo = 0, hi = NN;
    while (lo < hi) {
        int m = (lo + hi) >> 1;
        if (idx_at(batch, m, is64) < g) lo = m + 1;
        else hi = m;
    }
    g_start[g] = lo;
}

__global__ void __launch_bounds__(512) k_pool() {
    __shared__ float part[4][DH];
    int g = blockIdx.x;
    int c = threadIdx.x & 127;
    int q = threadIdx.x >> 7;
    int s = g_start[g], e = g_start[g + 1];
    int cnt = e - s;
    int chunk = (cnt + 3) >> 2;
    int rs = s + q * chunk;
    int re = min(rs + chunk, e);
    float sum = 0.f;
    for (int r = rs; r < re; r++) sum += g_x2[r * DH + c];
    part[q][c] = sum;
    __syncthreads();
    if (q == 0) {
        float tot = part[0][c] + part[1][c] + part[2][c] + part[3][c];
        g_pool[g * DH + c] = tot / (float)max(cnt, 1);
    }
}

__global__ void k_fc(const float* __restrict__ fcW, const float* __restrict__ fcb) {
    __shared__ float pr[DH];
    int g = blockIdx.x, o = threadIdx.x;
    pr[o] = g_pool[g * DH + o];
    __syncthreads();
    float acc = fcb[o];
#pragma unroll 4
    for (int k = 0; k < DH; k++) acc += pr[k] * fcW[k * DH + o];
    g_logits[g * DH + o] = acc;
}

__global__ void k_bn(const float* __restrict__ bng, const float* __restrict__ bnb,
                     float* __restrict__ out) {
    int o = threadIdx.x;
    float mu = 0.f;
    for (int g = 0; g < GG; g++) mu += g_logits[g * DH + o];
    mu *= (1.f / GG);
    float var = 0.f;
    for (int g = 0; g < GG; g++) {
        float d = g_logits[g * DH + o] - mu;
        var += d * d;
    }
    var *= (1.f / GG);
    float sc = rsqrtf(var + EPSF);
    float gg = bng[o], bb = bnb[o];
    for (int g = 0; g < GG; g++)
        out[g * DH + o] = (g_logits[g * DH + o] - mu) * sc * gg + bb;
}

// ---------------- launch ----------------
extern "C" void kernel_launch(void* const* d_in, const int* in_sizes, int n_in,
                              void* d_out, int out_size) {
    const float* x    = (const float*)d_in[0];
    const void*  ei   = d_in[1];
    const void*  bat  = d_in[2];
    const float* W1   = (const float*)d_in[3];
    const float* as1  = (const float*)d_in[4];
    const float* ad1  = (const float*)d_in[5];
    const float* b1   = (const float*)d_in[6];
    const float* W2   = (const float*)d_in[7];
    const float* as2  = (const float*)d_in[8];
    const float* ad2  = (const float*)d_in[9];
    const float* b2   = (const float*)d_in[10];
    const float* ln1g = (const float*)d_in[11];
    const float* ln1b = (const float*)d_in[12];
    const float* ln2g = (const float*)d_in[13];
    const float* ln2b = (const float*)d_in[14];
    const float* fcW  = (const float*)d_in[15];
    const float* fcb  = (const float*)d_in[16];
    const float* bng  = (const float*)d_in[17];
    const float* bnb  = (const float*)d_in[18];
    float* out = (float*)d_out;
    int E = in_sizes[1] / 2;

    cudaFuncSetAttribute(k_hmma, cudaFuncAttributeMaxDynamicSharedMemorySize, HMMA_SMEM);

    // CSR build + W prep
    k_detect<<<1, 256>>>((const int*)ei);
    k_zero<<<98, 512>>>();
    k_wprep<<<128, 256>>>(W1, W2);
    k_hist<<<512, 256>>>(ei, E);
    k_scan_bsum<<<SCAN_NB, SCAN_B>>>();
    k_scan_top<<<1, 256>>>();
    k_scan_expand<<<SCAN_NB, SCAN_B>>>();
    k_scatter<<<512, 256>>>(ei, E);

    // layer 1
    k_hmma<<<TILES, 256, HMMA_SMEM>>>(x, 0, as1, ad1);
    k_agg<1><<<NN / 8, 256>>>(b1, ln1g, ln1b);

    // layer 2
    k_hmma<<<TILES, 256, HMMA_SMEM>>>(nullptr, 1, as2, ad2);
    k_agg<2><<<NN / 8, 256>>>(b2, ln2g, ln2b);

    // pool + fc + bn
    k_bounds<<<1, 128>>>(bat);
    k_pool<<<GG, 512>>>();
    k_fc<<<GG, 128>>>(fcW, fcb);
    k_bn<<<1, 128>>>(bng, bnb, out);
}

// round 8
// speedup vs baseline: 1.4560x; 1.0429x over previous
#include <cuda_runtime.h>
#include <cuda_bf16.h>
#include <cstdint>

#define NN 50000
#define DH 128
#define GG 64
#define EPSF 1e-5f
#define EMAX 800000
#define ETOTMAX (EMAX + NN)
#define SCAN_B 256
#define SCAN_NB ((NN + SCAN_B - 1) / SCAN_B)   // 196
#define TILES ((NN + 127) / 128)               // 391
#define LDS_STRIDE 136                         // bf16 elems per smem row (68 words % 32 == 4)

// ---------------- scratch (static device globals; no allocations) ----------------
__device__ float g_h[NN * DH];
__device__ float g_x2[NN * DH];
__device__ float g_als[NN];
__device__ float g_ald[NN];
__device__ int   g_deg[NN];
__device__ int   g_cur[NN];
__device__ int   g_off[NN + 1];
__device__ int   g_csrc[ETOTMAX];
__device__ int   g_is64;
__device__ int   g_bsum[SCAN_NB];
__device__ int   g_boff[SCAN_NB];
__device__ float g_logits[GG * DH];
// W^T split-bf16: [layer][n*128+k]
__device__ __align__(16) __nv_bfloat16 g_Bh[2][16384];
__device__ __align__(16) __nv_bfloat16 g_Bl[2][16384];

__device__ __forceinline__ int idx_at(const void* p, long long i, int is64) {
    if (is64) return (int)((const long long*)p)[i];
    return ((const int*)p)[i];
}

// ---------------- dtype detection ----------------
__global__ void k_detect(const int* ei32) {
    __shared__ int bad;
    if (threadIdx.x == 0) bad = 0;
    __syncthreads();
    int t = threadIdx.x;
    int any = 0;
#pragma unroll
    for (int i = 0; i < 8; i++)
        if (ei32[2 * (t * 8 + i) + 1] != 0) any = 1;
    if (any) atomicOr(&bad, 1);
    __syncthreads();
    if (t == 0) g_is64 = !bad;
}

__global__ void k_zero() {
    for (int i = blockIdx.x * blockDim.x + threadIdx.x; i < NN;
         i += gridDim.x * blockDim.x)
        g_deg[i] = 0;
}

// ---------------- CSR build ----------------
__global__ void k_hist(const void* ei, int E) {
    int is64 = g_is64;
    int tot = E + NN;
    for (int i = blockIdx.x * blockDim.x + threadIdx.x; i < tot;
         i += gridDim.x * blockDim.x) {
        int dst = (i < E) ? idx_at(ei, (long long)E + i, is64) : (i - E);
        atomicAdd(&g_deg[dst], 1);
    }
}

__global__ void __launch_bounds__(SCAN_B) k_scan_bsum() {
    __shared__ int ss[SCAN_B];
    int id = blockIdx.x * SCAN_B + threadIdx.x;
    ss[threadIdx.x] = (id < NN) ? g_deg[id] : 0;
    __syncthreads();
    for (int o = SCAN_B / 2; o > 0; o >>= 1) {
        if (threadIdx.x < o) ss[threadIdx.x] += ss[threadIdx.x + o];
        __syncthreads();
    }
    if (threadIdx.x == 0) g_bsum[blockIdx.x] = ss[0];
}

__global__ void __launch_bounds__(256) k_scan_top() {
    __shared__ int ss[256];
    int t = threadIdx.x;
    int v = (t < SCAN_NB) ? g_bsum[t] : 0;
    ss[t] = v;
    __syncthreads();
    for (int o = 1; o < 256; o <<= 1) {
        int u = (t >= o) ? ss[t - o] : 0;
        __syncthreads();
        ss[t] += u;
        __syncthreads();
    }
    if (t < SCAN_NB) g_boff[t] = ss[t] - v;
}

__global__ void __launch_bounds__(SCAN_B) k_scan_expand() {
    __shared__ int ss[SCAN_B];
    int t = threadIdx.x;
    int id = blockIdx.x * SCAN_B + t;
    int v = (id < NN) ? g_deg[id] : 0;
    ss[t] = v;
    __syncthreads();
    for (int o = 1; o < SCAN_B; o <<= 1) {
        int u = (t >= o) ? ss[t - o] : 0;
        __syncthreads();
        ss[t] += u;
        __syncthreads();
    }
    int base = g_boff[blockIdx.x];
    if (id < NN) {
        int excl = base + ss[t] - v;
        g_off[id] = excl;
        g_cur[id] = excl;                 // seed scatter cursor with offset
        if (id == NN - 1) g_off[NN] = base + ss[t];
    }
}

__global__ void k_scatter(const void* ei, int E) {
    int is64 = g_is64;
    int tot = E + NN;
    for (int i = blockIdx.x * blockDim.x + threadIdx.x; i < tot;
         i += gridDim.x * blockDim.x) {
        int src, dst;
        if (i < E) {
            src = idx_at(ei, i, is64);
            dst = idx_at(ei, (long long)E + i, is64);
        } else {
            src = i - E;
            dst = i - E;
        }
        int pos = atomicAdd(&g_cur[dst], 1);  // absolute position
        g_csrc[pos] = src;
    }
}

// ---------------- W prep: fp32 W[k][n] -> split bf16 W^T[n][k] ----------------
__global__ void k_wprep(const float* __restrict__ W1, const float* __restrict__ W2) {
    int id = blockIdx.x * blockDim.x + threadIdx.x;   // 0..32767
    int layer = id >> 14;
    int e = id & 16383;
    int k = e >> 7, n = e & 127;
    const float* W = layer ? W2 : W1;
    float w = W[k * 128 + n];
    __nv_bfloat16 hi = __float2bfloat16(w);
    float rem = w - __bfloat162float(hi);
    g_Bh[layer][n * 128 + k] = hi;
    g_Bl[layer][n * 128 + k] = __float2bfloat16(rem);
}

// ---------------- mma.sync bf16 split GEMM + fused attention logits ----------------
__device__ __forceinline__ void mma16816(float d[4], const uint32_t a[4],
                                         const uint32_t b[2]) {
    asm volatile(
        "mma.sync.aligned.m16n8k16.row.col.f32.bf16.bf16.f32 "
        "{%0,%1,%2,%3}, {%4,%5,%6,%7}, {%8,%9}, {%0,%1,%2,%3};"
        : "+f"(d[0]), "+f"(d[1]), "+f"(d[2]), "+f"(d[3])
        : "r"(a[0]), "r"(a[1]), "r"(a[2]), "r"(a[3]), "r"(b[0]), "r"(b[1]));
}

__device__ __forceinline__ void mma_pass(const __nv_bfloat16* __restrict__ A,
                                         const __nv_bfloat16* __restrict__ B,
                                         int wr, int wc, int gid, int tig,
                                         float acc[2][8][4]) {
#pragma unroll
    for (int ks = 0; ks < 8; ks++) {
        int k0 = ks * 16;
        uint32_t a[2][4];
#pragma unroll
        for (int mi = 0; mi < 2; mi++) {
            const __nv_bfloat16* p = A + (wr + mi * 16 + gid) * LDS_STRIDE + k0 + tig * 2;
            a[mi][0] = *(const uint32_t*)(p);
            a[mi][1] = *(const uint32_t*)(p + 8 * LDS_STRIDE);
            a[mi][2] = *(const uint32_t*)(p + 8);
            a[mi][3] = *(const uint32_t*)(p + 8 * LDS_STRIDE + 8);
        }
        uint32_t b[8][2];
#pragma unroll
        for (int ni = 0; ni < 8; ni++) {
            const __nv_bfloat16* p = B + (wc + ni * 8 + gid) * LDS_STRIDE + k0 + tig * 2;
            b[ni][0] = *(const uint32_t*)(p);
            b[ni][1] = *(const uint32_t*)(p + 8);
        }
#pragma unroll
        for (int mi = 0; mi < 2; mi++)
#pragma unroll
            for (int ni = 0; ni < 8; ni++) mma16816(acc[mi][ni], a[mi], b[ni]);
    }
}

// smem: A[128][136] bf16, Bh[128][136], Bl[128][136], then reduce arrays
#define SM_BH  (128 * LDS_STRIDE)
#define SM_BL  (2 * 128 * LDS_STRIDE)
#define SM_FLT (3 * 128 * LDS_STRIDE)
#define HMMA_SMEM (SM_FLT * 2 + (256 + 256 + 128 + 128) * 4)

__global__ void __launch_bounds__(256, 2)
k_hmma(const float* __restrict__ Xext, int layer,
       const float* __restrict__ asrc, const float* __restrict__ adst) {
    extern __shared__ __align__(16) char sm[];
    __nv_bfloat16* As = (__nv_bfloat16*)sm;
    __nv_bfloat16* Bh = As + SM_BH;
    __nv_bfloat16* Bl = As + SM_BL;
    float* sps = (float*)(sm + SM_FLT * 2);     // [128][2]
    float* spd = sps + 256;
    float* s_as = spd + 256;
    float* s_ad = s_as + 128;

    const float* X = layer ? g_x2 : Xext;
    int tid = threadIdx.x;
    int wid = tid >> 5, lane = tid & 31;
    int gid = lane >> 2, tig = lane & 3;
    int wr = (wid & 3) * 32;
    int wc = (wid >> 2) * 64;
    int rowBase = blockIdx.x * 128;

    {
        const int4* gh = (const int4*)g_Bh[layer];
        const int4* gl = (const int4*)g_Bl[layer];
#pragma unroll
        for (int i = tid; i < 2048; i += 256) {
            int r = i >> 4, c = i & 15;
            *(int4*)((char*)Bh + r * (LDS_STRIDE * 2) + c * 16) = gh[i];
            *(int4*)((char*)Bl + r * (LDS_STRIDE * 2) + c * 16) = gl[i];
        }
    }
    if (tid < 128) {
        s_as[tid] = asrc[tid];
        s_ad[tid] = adst[tid];
    }
#pragma unroll
    for (int i = 0; i < 32; i++) {
        int f = tid + i * 256;
        int r = f >> 6, kp = f & 63;
        int row = rowBase + r;
        float2 v = make_float2(0.f, 0.f);
        if (row < NN) v = *(const float2*)&X[row * DH + kp * 2];
        *(__nv_bfloat162*)&As[r * LDS_STRIDE + kp * 2] =
            __halves2bfloat162(__float2bfloat16(v.x), __float2bfloat16(v.y));
    }
    __syncthreads();

    float acc[2][8][4];
#pragma unroll
    for (int mi = 0; mi < 2; mi++)
#pragma unroll
        for (int ni = 0; ni < 8; ni++)
#pragma unroll
            for (int q = 0; q < 4; q++) acc[mi][ni][q] = 0.f;

    mma_pass(As, Bh, wr, wc, gid, tig, acc);    // hi * hi
    mma_pass(As, Bl, wr, wc, gid, tig, acc);    // hi * lo
    __syncthreads();
#pragma unroll
    for (int i = 0; i < 32; i++) {
        int f = tid + i * 256;
        int r = f >> 6, kp = f & 63;
        int row = rowBase + r;
        float2 v = make_float2(0.f, 0.f);
        if (row < NN) v = *(const float2*)&X[row * DH + kp * 2];
        float lx = v.x - __bfloat162float(__float2bfloat16(v.x));
        float ly = v.y - __bfloat162float(__float2bfloat16(v.y));
        *(__nv_bfloat162*)&As[r * LDS_STRIDE + kp * 2] =
            __halves2bfloat162(__float2bfloat16(lx), __float2bfloat16(ly));
    }
    __syncthreads();
    mma_pass(As, Bh, wr, wc, gid, tig, acc);    // lo * hi

    float ps[4] = {0.f, 0.f, 0.f, 0.f};
    float pd[4] = {0.f, 0.f, 0.f, 0.f};
#pragma unroll
    for (int mi = 0; mi < 2; mi++) {
#pragma unroll
        for (int ni = 0; ni < 8; ni++) {
            int col = wc + ni * 8 + tig * 2;
            float a0 = s_as[col], a1 = s_as[col + 1];
            float d0 = s_ad[col], d1 = s_ad[col + 1];
            float* v = acc[mi][ni];
            ps[mi * 2 + 0] += v[0] * a0 + v[1] * a1;
            pd[mi * 2 + 0] += v[0] * d0 + v[1] * d1;
            ps[mi * 2 + 1] += v[2] * a0 + v[3] * a1;
            pd[mi * 2 + 1] += v[2] * d0 + v[3] * d1;
            int r0 = rowBase + wr + mi * 16 + gid;
            if (r0 < NN)
                *(float2*)&g_h[r0 * DH + col] = make_float2(v[0], v[1]);
            if (r0 + 8 < NN)
                *(float2*)&g_h[(r0 + 8) * DH + col] = make_float2(v[2], v[3]);
        }
    }
#pragma unroll
    for (int j = 0; j < 4; j++) {
#pragma unroll
        for (int o = 1; o <= 2; o <<= 1) {
            ps[j] += __shfl_xor_sync(0xffffffffu, ps[j], o);
            pd[j] += __shfl_xor_sync(0xffffffffu, pd[j], o);
        }
    }
    if (tig == 0) {
        int ch = wid >> 2;
#pragma unroll
        for (int j = 0; j < 4; j++) {
            int rloc = wr + (j >> 1) * 16 + (j & 1) * 8 + gid;
            sps[rloc * 2 + ch] = ps[j];
            spd[rloc * 2 + ch] = pd[j];
        }
    }
    __syncthreads();
    if (tid < 128 && rowBase + tid < NN) {
        g_als[rowBase + tid] = sps[tid * 2] + sps[tid * 2 + 1];
        g_ald[rowBase + tid] = spd[tid * 2] + spd[tid * 2 + 1];
    }
}

// ---------------- warp-per-node aggregation: lane-parallel edge prefetch ----------------
// out[v] = sum_j e_j * h[src_j] / sum_j e_j ; e_j = exp(lrelu(als[src_j]+ald[v]))
template <int MODE>
__global__ void __launch_bounds__(256) k_agg(const float* __restrict__ bias,
                                             const float* __restrict__ lng,
                                             const float* __restrict__ lnb) {
    int w = (blockIdx.x * blockDim.x + threadIdx.x) >> 5;
    int lane = threadIdx.x & 31;
    if (w >= NN) return;
    int js = g_off[w], je = g_off[w + 1];
    float aldv = g_ald[w];
    float ax = 0.f, ay = 0.f, az = 0.f, aw = 0.f, z = 0.f;

    for (int base = js; base < je; base += 32) {
        int cnt = min(32, je - base);
        // lane-parallel: each lane grabs one edge index + its source logit
        int idx = w;
        float ef = 0.f;
        if (lane < cnt) {
            idx = g_csrc[base + lane];
            float a = g_als[idx] + aldv;
            a = a > 0.f ? a : 0.2f * a;
            ef = __expf(a);
        }
        int j = 0;
        // 4-wide: 4 independent h-row loads in flight
        for (; j + 4 <= cnt; j += 4) {
            int s0 = __shfl_sync(0xffffffffu, idx, j);
            int s1 = __shfl_sync(0xffffffffu, idx, j + 1);
            int s2 = __shfl_sync(0xffffffffu, idx, j + 2);
            int s3 = __shfl_sync(0xffffffffu, idx, j + 3);
            float e0 = __shfl_sync(0xffffffffu, ef, j);
            float e1 = __shfl_sync(0xffffffffu, ef, j + 1);
            float e2 = __shfl_sync(0xffffffffu, ef, j + 2);
            float e3 = __shfl_sync(0xffffffffu, ef, j + 3);
            float4 h0 = *(const float4*)&g_h[s0 * DH + lane * 4];
            float4 h1 = *(const float4*)&g_h[s1 * DH + lane * 4];
            float4 h2 = *(const float4*)&g_h[s2 * DH + lane * 4];
            float4 h3 = *(const float4*)&g_h[s3 * DH + lane * 4];
            ax += e0 * h0.x + e1 * h1.x + e2 * h2.x + e3 * h3.x;
            ay += e0 * h0.y + e1 * h1.y + e2 * h2.y + e3 * h3.y;
            az += e0 * h0.z + e1 * h1.z + e2 * h2.z + e3 * h3.z;
            aw += e0 * h0.w + e1 * h1.w + e2 * h2.w + e3 * h3.w;
            z += e0 + e1 + e2 + e3;
        }
        for (; j < cnt; j++) {
            int s = __shfl_sync(0xffffffffu, idx, j);
            float e = __shfl_sync(0xffffffffu, ef, j);
            float4 hv = *(const float4*)&g_h[s * DH + lane * 4];
            ax += e * hv.x;
            ay += e * hv.y;
            az += e * hv.z;
            aw += e * hv.w;
            z += e;
        }
    }
    float inv = 1.f / z;
    float4 b4 = *(const float4*)&bias[lane * 4];
    float c0 = ax * inv + b4.x;
    float c1 = ay * inv + b4.y;
    float c2 = az * inv + b4.z;
    float c3 = aw * inv + b4.w;
    if (MODE == 1) {
        c0 = fmaxf(c0, 0.f); c1 = fmaxf(c1, 0.f);
        c2 = fmaxf(c2, 0.f); c3 = fmaxf(c3, 0.f);
    }
    float tot = c0 + c1 + c2 + c3;
#pragma unroll
    for (int o = 16; o > 0; o >>= 1) tot += __shfl_xor_sync(0xffffffffu, tot, o);
    float mu = tot * (1.f / DH);
    float d0 = c0 - mu, d1 = c1 - mu, d2 = c2 - mu, d3 = c3 - mu;
    float ssq = d0 * d0 + d1 * d1 + d2 * d2 + d3 * d3;
#pragma unroll
    for (int o = 16; o > 0; o >>= 1) ssq += __shfl_xor_sync(0xffffffffu, ssq, o);
    float var = ssq * (1.f / DH);
    float sc = rsqrtf(var + EPSF);
    float4 g4 = *(const float4*)&lng[lane * 4];
    float4 bb = *(const float4*)&lnb[lane * 4];
    float o0 = d0 * sc * g4.x + bb.x;
    float o1 = d1 * sc * g4.y + bb.y;
    float o2 = d2 * sc * g4.z + bb.z;
    float o3 = d3 * sc * g4.w + bb.w;
    if (MODE == 2) {
        o0 = fmaxf(o0, 0.f); o1 = fmaxf(o1, 0.f);
        o2 = fmaxf(o2, 0.f); o3 = fmaxf(o3, 0.f);
    }
    *(float4*)&g_x2[w * DH + lane * 4] = make_float4(o0, o1, o2, o3);
}

// ---------------- fused bounds + pool + fc ----------------
__global__ void __launch_bounds__(512) k_poolfc(const void* batch,
                                                const float* __restrict__ fcW,
                                                const float* __restrict__ fcb) {
    __shared__ float part[4][DH];
    __shared__ float pr[DH];
    __shared__ int sbound[2];
    int g = blockIdx.x;
    int t = threadIdx.x;
    if (t < 2) {
        int is64 = g_is64;
        int target = g + t;
        int lo = 0, hi = NN;
        while (lo < hi) {
            int m = (lo + hi) >> 1;
            if (idx_at(batch, m, is64) < target) lo = m + 1;
            else hi = m;
        }
        sbound[t] = lo;
    }
    __syncthreads();
    int s = sbound[0], e = sbound[1];
    int c = t & 127;
    int q = t >> 7;
    int cnt = e - s;
    int chunk = (cnt + 3) >> 2;
    int rs = s + q * chunk;
    int re = min(rs + chunk, e);
    float sum = 0.f;
    for (int r = rs; r < re; r++) sum += g_x2[r * DH + c];
    part[q][c] = sum;
    __syncthreads();
    if (q == 0) {
        float tot2 = part[0][c] + part[1][c] + part[2][c] + part[3][c];
        pr[c] = tot2 / (float)max(cnt, 1);
    }
    __syncthreads();
    if (t < 128) {
        float acc = fcb[t];
#pragma unroll 4
        for (int k = 0; k < DH; k++) acc += pr[k] * fcW[k * DH + t];
        g_logits[g * DH + t] = acc;
    }
}

__global__ void k_bn(const float* __restrict__ bng, const float* __restrict__ bnb,
                     float* __restrict__ out) {
    int o = threadIdx.x;
    float mu = 0.f;
    for (int g = 0; g < GG; g++) mu += g_logits[g * DH + o];
    mu *= (1.f / GG);
    float var = 0.f;
    for (int g = 0; g < GG; g++) {
        float d = g_logits[g * DH + o] - mu;
        var += d * d;
    }
    var *= (1.f / GG);
    float sc = rsqrtf(var + EPSF);
    float gg = bng[o], bb = bnb[o];
    for (int g = 0; g < GG; g++)
        out[g * DH + o] = (g_logits[g * DH + o] - mu) * sc * gg + bb;
}

// ---------------- launch ----------------
extern "C" void kernel_launch(void* const* d_in, const int* in_sizes, int n_in,
                              void* d_out, int out_size) {
    const float* x    = (const float*)d_in[0];
    const void*  ei   = d_in[1];
    const void*  bat  = d_in[2];
    const float* W1   = (const float*)d_in[3];
    const float* as1  = (const float*)d_in[4];
    const float* ad1  = (const float*)d_in[5];
    const float* b1   = (const float*)d_in[6];
    const float* W2   = (const float*)d_in[7];
    const float* as2  = (const float*)d_in[8];
    const float* ad2  = (const float*)d_in[9];
    const float* b2   = (const float*)d_in[10];
    const float* ln1g = (const float*)d_in[11];
    const float* ln1b = (const float*)d_in[12];
    const float* ln2g = (const float*)d_in[13];
    const float* ln2b = (const float*)d_in[14];
    const float* fcW  = (const float*)d_in[15];
    const float* fcb  = (const float*)d_in[16];
    const float* bng  = (const float*)d_in[17];
    const float* bnb  = (const float*)d_in[18];
    float* out = (float*)d_out;
    int E = in_sizes[1] / 2;

    cudaFuncSetAttribute(k_hmma, cudaFuncAttributeMaxDynamicSharedMemorySize, HMMA_SMEM);

    // CSR build + W prep
    k_detect<<<1, 256>>>((const int*)ei);
    k_zero<<<98, 512>>>();
    k_wprep<<<128, 256>>>(W1, W2);
    k_hist<<<1024, 256>>>(ei, E);
    k_scan_bsum<<<SCAN_NB, SCAN_B>>>();
    k_scan_top<<<1, 256>>>();
    k_scan_expand<<<SCAN_NB, SCAN_B>>>();
    k_scatter<<<1024, 256>>>(ei, E);

    // layer 1
    k_hmma<<<TILES, 256, HMMA_SMEM>>>(x, 0, as1, ad1);
    k_agg<1><<<NN / 8, 256>>>(b1, ln1g, ln1b);

    // layer 2
    k_hmma<<<TILES, 256, HMMA_SMEM>>>(nullptr, 1, as2, ad2);
    k_agg<2><<<NN / 8, 256>>>(b2, ln2g, ln2b);

    // pool + fc + bn
    k_poolfc<<<GG, 512>>>(bat, fcW, fcb);
    k_bn<<<1, 128>>>(bng, bnb, out);
}

// round 9
// speedup vs baseline: 1.6279x; 1.1181x over previous
#include <cuda_runtime.h>
#include <cuda_bf16.h>
#include <cuda_fp16.h>
#include <cstdint>

#define NN 50000
#define DH 128
#define GG 64
#define EPSF 1e-5f
#define EMAX 800000
#define ETOTMAX (EMAX + NN)
#define SCAN_B 256
#define SCAN_NB ((NN + SCAN_B - 1) / SCAN_B)   // 196
#define TILES ((NN + 127) / 128)               // 391
#define LDS_STRIDE 136

// ---------------- scratch ----------------
__device__ __half g_h[NN * DH];                // fp16 h (agg-only consumer)
__device__ float g_x2[NN * DH];
__device__ float g_als[NN];
__device__ float g_ald[NN];
__device__ int   g_deg[NN];
__device__ int   g_cur[NN];
__device__ int   g_off[NN + 1];
__device__ int   g_csrc[ETOTMAX];
__device__ int   g_is64;
__device__ int   g_bsum[SCAN_NB];
__device__ int   g_boff[SCAN_NB];
__device__ float g_logits[GG * DH];
__device__ __align__(16) __nv_bfloat16 g_Bh[2][16384];
__device__ __align__(16) __nv_bfloat16 g_Bl[2][16384];

__device__ __forceinline__ int idx_at(const void* p, long long i, int is64) {
    if (is64) return (int)((const long long*)p)[i];
    return ((const int*)p)[i];
}

// ---------------- dtype detection ----------------
__global__ void k_detect(const int* ei32) {
    __shared__ int bad;
    if (threadIdx.x == 0) bad = 0;
    __syncthreads();
    int t = threadIdx.x;
    int any = 0;
#pragma unroll
    for (int i = 0; i < 8; i++)
        if (ei32[2 * (t * 8 + i) + 1] != 0) any = 1;
    if (any) atomicOr(&bad, 1);
    __syncthreads();
    if (t == 0) g_is64 = !bad;
}

__global__ void k_zero() {
    for (int i = blockIdx.x * blockDim.x + threadIdx.x; i < NN;
         i += gridDim.x * blockDim.x)
        g_deg[i] = 0;
}

// ---------------- CSR build (pair-vectorized) ----------------
__global__ void k_hist(const void* ei, int E) {
    int is64 = g_is64;
    int half = E >> 1;
    int odd = E & 1;
    int tot = half + odd + NN;
    for (int i = blockIdx.x * blockDim.x + threadIdx.x; i < tot;
         i += gridDim.x * blockDim.x) {
        if (i < half) {
            int d0, d1;
            if (is64) {
                longlong2 v = ((const longlong2*)((const long long*)ei + E))[i];
                d0 = (int)v.x; d1 = (int)v.y;
            } else {
                int2 v = ((const int2*)((const int*)ei + E))[i];
                d0 = v.x; d1 = v.y;
            }
            atomicAdd(&g_deg[d0], 1);
            atomicAdd(&g_deg[d1], 1);
        } else if (odd && i == half) {
            atomicAdd(&g_deg[idx_at(ei, 2LL * E - 1, is64)], 1);
        } else {
            atomicAdd(&g_deg[i - half - odd], 1);
        }
    }
}

__global__ void __launch_bounds__(SCAN_B) k_scan_bsum() {
    __shared__ int ss[SCAN_B];
    int id = blockIdx.x * SCAN_B + threadIdx.x;
    ss[threadIdx.x] = (id < NN) ? g_deg[id] : 0;
    __syncthreads();
    for (int o = SCAN_B / 2; o > 0; o >>= 1) {
        if (threadIdx.x < o) ss[threadIdx.x] += ss[threadIdx.x + o];
        __syncthreads();
    }
    if (threadIdx.x == 0) g_bsum[blockIdx.x] = ss[0];
}

__global__ void __launch_bounds__(256) k_scan_top() {
    __shared__ int ss[256];
    int t = threadIdx.x;
    int v = (t < SCAN_NB) ? g_bsum[t] : 0;
    ss[t] = v;
    __syncthreads();
    for (int o = 1; o < 256; o <<= 1) {
        int u = (t >= o) ? ss[t - o] : 0;
        __syncthreads();
        ss[t] += u;
        __syncthreads();
    }
    if (t < SCAN_NB) g_boff[t] = ss[t] - v;
}

__global__ void __launch_bounds__(SCAN_B) k_scan_expand() {
    __shared__ int ss[SCAN_B];
    int t = threadIdx.x;
    int id = blockIdx.x * SCAN_B + t;
    int v = (id < NN) ? g_deg[id] : 0;
    ss[t] = v;
    __syncthreads();
    for (int o = 1; o < SCAN_B; o <<= 1) {
        int u = (t >= o) ? ss[t - o] : 0;
        __syncthreads();
        ss[t] += u;
        __syncthreads();
    }
    int base = g_boff[blockIdx.x];
    if (id < NN) {
        int excl = base + ss[t] - v;
        g_off[id] = excl;
        g_cur[id] = excl;
        if (id == NN - 1) g_off[NN] = base + ss[t];
    }
}

__global__ void k_scatter(const void* ei, int E) {
    int is64 = g_is64;
    int half = E >> 1;
    int odd = E & 1;
    int tot = half + odd + NN;
    for (int i = blockIdx.x * blockDim.x + threadIdx.x; i < tot;
         i += gridDim.x * blockDim.x) {
        if (i < half) {
            int s0, s1, d0, d1;
            if (is64) {
                longlong2 s = ((const longlong2*)ei)[i];
                longlong2 d = ((const longlong2*)((const long long*)ei + E))[i];
                s0 = (int)s.x; s1 = (int)s.y;
                d0 = (int)d.x; d1 = (int)d.y;
            } else {
                int2 s = ((const int2*)ei)[i];
                int2 d = ((const int2*)((const int*)ei + E))[i];
                s0 = s.x; s1 = s.y;
                d0 = d.x; d1 = d.y;
            }
            g_csrc[atomicAdd(&g_cur[d0], 1)] = s0;
            g_csrc[atomicAdd(&g_cur[d1], 1)] = s1;
        } else if (odd && i == half) {
            int s = idx_at(ei, E - 1, is64);
            int d = idx_at(ei, 2LL * E - 1, is64);
            g_csrc[atomicAdd(&g_cur[d], 1)] = s;
        } else {
            int v = i - half - odd;
            g_csrc[atomicAdd(&g_cur[v], 1)] = v;
        }
    }
}

// ---------------- W prep ----------------
__global__ void k_wprep(const float* __restrict__ W1, const float* __restrict__ W2) {
    int id = blockIdx.x * blockDim.x + threadIdx.x;
    int layer = id >> 14;
    int e = id & 16383;
    int k = e >> 7, n = e & 127;
    const float* W = layer ? W2 : W1;
    float w = W[k * 128 + n];
    __nv_bfloat16 hi = __float2bfloat16(w);
    g_Bh[layer][n * 128 + k] = hi;
    g_Bl[layer][n * 128 + k] = __float2bfloat16(w - __bfloat162float(hi));
}

// ---------------- mma.sync bf16 split GEMM + fused attention logits ----------------
__device__ __forceinline__ void mma16816(float d[4], const uint32_t a[4],
                                         const uint32_t b[2]) {
    asm volatile(
        "mma.sync.aligned.m16n8k16.row.col.f32.bf16.bf16.f32 "
        "{%0,%1,%2,%3}, {%4,%5,%6,%7}, {%8,%9}, {%0,%1,%2,%3};"
        : "+f"(d[0]), "+f"(d[1]), "+f"(d[2]), "+f"(d[3])
        : "r"(a[0]), "r"(a[1]), "r"(a[2]), "r"(a[3]), "r"(b[0]), "r"(b[1]));
}

__device__ __forceinline__ void mma_pass(const __nv_bfloat16* __restrict__ A,
                                         const __nv_bfloat16* __restrict__ B,
                                         int wr, int wc, int gid, int tig,
                                         float acc[2][8][4]) {
#pragma unroll
    for (int ks = 0; ks < 8; ks++) {
        int k0 = ks * 16;
        uint32_t a[2][4];
#pragma unroll
        for (int mi = 0; mi < 2; mi++) {
            const __nv_bfloat16* p = A + (wr + mi * 16 + gid) * LDS_STRIDE + k0 + tig * 2;
            a[mi][0] = *(const uint32_t*)(p);
            a[mi][1] = *(const uint32_t*)(p + 8 * LDS_STRIDE);
            a[mi][2] = *(const uint32_t*)(p + 8);
            a[mi][3] = *(const uint32_t*)(p + 8 * LDS_STRIDE + 8);
        }
        uint32_t b[8][2];
#pragma unroll
        for (int ni = 0; ni < 8; ni++) {
            const __nv_bfloat16* p = B + (wc + ni * 8 + gid) * LDS_STRIDE + k0 + tig * 2;
            b[ni][0] = *(const uint32_t*)(p);
            b[ni][1] = *(const uint32_t*)(p + 8);
        }
#pragma unroll
        for (int mi = 0; mi < 2; mi++)
#pragma unroll
            for (int ni = 0; ni < 8; ni++) mma16816(acc[mi][ni], a[mi], b[ni]);
    }
}

#define SM_BH  (128 * LDS_STRIDE)
#define SM_BL  (2 * 128 * LDS_STRIDE)
#define SM_FLT (3 * 128 * LDS_STRIDE)
#define HMMA_SMEM (SM_FLT * 2 + (256 + 256 + 128 + 128) * 4)

__global__ void __launch_bounds__(256, 2)
k_hmma(const float* __restrict__ Xext, int layer,
       const float* __restrict__ asrc, const float* __restrict__ adst) {
    extern __shared__ __align__(16) char sm[];
    __nv_bfloat16* As = (__nv_bfloat16*)sm;
    __nv_bfloat16* Bh = As + SM_BH;
    __nv_bfloat16* Bl = As + SM_BL;
    float* sps = (float*)(sm + SM_FLT * 2);
    float* spd = sps + 256;
    float* s_as = spd + 256;
    float* s_ad = s_as + 128;

    const float* X = layer ? g_x2 : Xext;
    int tid = threadIdx.x;
    int wid = tid >> 5, lane = tid & 31;
    int gid = lane >> 2, tig = lane & 3;
    int wr = (wid & 3) * 32;
    int wc = (wid >> 2) * 64;
    int rowBase = blockIdx.x * 128;

    {
        const int4* gh = (const int4*)g_Bh[layer];
        const int4* gl = (const int4*)g_Bl[layer];
#pragma unroll
        for (int i = tid; i < 2048; i += 256) {
            int r = i >> 4, c = i & 15;
            *(int4*)((char*)Bh + r * (LDS_STRIDE * 2) + c * 16) = gh[i];
            *(int4*)((char*)Bl + r * (LDS_STRIDE * 2) + c * 16) = gl[i];
        }
    }
    if (tid < 128) {
        s_as[tid] = asrc[tid];
        s_ad[tid] = adst[tid];
    }
#pragma unroll
    for (int i = 0; i < 32; i++) {
        int f = tid + i * 256;
        int r = f >> 6, kp = f & 63;
        int row = rowBase + r;
        float2 v = make_float2(0.f, 0.f);
        if (row < NN) v = *(const float2*)&X[row * DH + kp * 2];
        *(__nv_bfloat162*)&As[r * LDS_STRIDE + kp * 2] =
            __halves2bfloat162(__float2bfloat16(v.x), __float2bfloat16(v.y));
    }
    __syncthreads();

    float acc[2][8][4];
#pragma unroll
    for (int mi = 0; mi < 2; mi++)
#pragma unroll
        for (int ni = 0; ni < 8; ni++)
#pragma unroll
            for (int q = 0; q < 4; q++) acc[mi][ni][q] = 0.f;

    mma_pass(As, Bh, wr, wc, gid, tig, acc);
    mma_pass(As, Bl, wr, wc, gid, tig, acc);
    __syncthreads();
#pragma unroll
    for (int i = 0; i < 32; i++) {
        int f = tid + i * 256;
        int r = f >> 6, kp = f & 63;
        int row = rowBase + r;
        float2 v = make_float2(0.f, 0.f);
        if (row < NN) v = *(const float2*)&X[row * DH + kp * 2];
        float lx = v.x - __bfloat162float(__float2bfloat16(v.x));
        float ly = v.y - __bfloat162float(__float2bfloat16(v.y));
        *(__nv_bfloat162*)&As[r * LDS_STRIDE + kp * 2] =
            __halves2bfloat162(__float2bfloat16(lx), __float2bfloat16(ly));
    }
    __syncthreads();
    mma_pass(As, Bh, wr, wc, gid, tig, acc);

    float ps[4] = {0.f, 0.f, 0.f, 0.f};
    float pd[4] = {0.f, 0.f, 0.f, 0.f};
#pragma unroll
    for (int mi = 0; mi < 2; mi++) {
#pragma unroll
        for (int ni = 0; ni < 8; ni++) {
            int col = wc + ni * 8 + tig * 2;
            float a0 = s_as[col], a1 = s_as[col + 1];
            float d0 = s_ad[col], d1 = s_ad[col + 1];
            float* v = acc[mi][ni];
            ps[mi * 2 + 0] += v[0] * a0 + v[1] * a1;
            pd[mi * 2 + 0] += v[0] * d0 + v[1] * d1;
            ps[mi * 2 + 1] += v[2] * a0 + v[3] * a1;
            pd[mi * 2 + 1] += v[2] * d0 + v[3] * d1;
            int r0 = rowBase + wr + mi * 16 + gid;
            if (r0 < NN)
                *(__half2*)&g_h[r0 * DH + col] = __floats2half2_rn(v[0], v[1]);
            if (r0 + 8 < NN)
                *(__half2*)&g_h[(r0 + 8) * DH + col] = __floats2half2_rn(v[2], v[3]);
        }
    }
#pragma unroll
    for (int j = 0; j < 4; j++) {
#pragma unroll
        for (int o = 1; o <= 2; o <<= 1) {
            ps[j] += __shfl_xor_sync(0xffffffffu, ps[j], o);
            pd[j] += __shfl_xor_sync(0xffffffffu, pd[j], o);
        }
    }
    if (tig == 0) {
        int ch = wid >> 2;
#pragma unroll
        for (int j = 0; j < 4; j++) {
            int rloc = wr + (j >> 1) * 16 + (j & 1) * 8 + gid;
            sps[rloc * 2 + ch] = ps[j];
            spd[rloc * 2 + ch] = pd[j];
        }
    }
    __syncthreads();
    if (tid < 128 && rowBase + tid < NN) {
        g_als[rowBase + tid] = sps[tid * 2] + sps[tid * 2 + 1];
        g_ald[rowBase + tid] = spd[tid * 2] + spd[tid * 2 + 1];
    }
}

// ---------------- warp-per-node aggregation (fp16 h rows) ----------------
template <int MODE>
__global__ void __launch_bounds__(256) k_agg(const float* __restrict__ bias,
                                             const float* __restrict__ lng,
                                             const float* __restrict__ lnb) {
    int w = (blockIdx.x * blockDim.x + threadIdx.x) >> 5;
    int lane = threadIdx.x & 31;
    if (w >= NN) return;
    int js = g_off[w], je = g_off[w + 1];
    float aldv = g_ald[w];
    float ax = 0.f, ay = 0.f, az = 0.f, aw = 0.f, z = 0.f;
    const uint2* hrow = (const uint2*)g_h;       // 32 uint2 per 128-half row

    for (int base = js; base < je; base += 32) {
        int cnt = min(32, je - base);
        int idx = w;
        float ef = 0.f;
        if (lane < cnt) {
            idx = g_csrc[base + lane];
            float a = g_als[idx] + aldv;
            a = a > 0.f ? a : 0.2f * a;
            ef = __expf(a);
        }
        int j = 0;
        for (; j + 4 <= cnt; j += 4) {
            int s0 = __shfl_sync(0xffffffffu, idx, j);
            int s1 = __shfl_sync(0xffffffffu, idx, j + 1);
            int s2 = __shfl_sync(0xffffffffu, idx, j + 2);
            int s3 = __shfl_sync(0xffffffffu, idx, j + 3);
            float e0 = __shfl_sync(0xffffffffu, ef, j);
            float e1 = __shfl_sync(0xffffffffu, ef, j + 1);
            float e2 = __shfl_sync(0xffffffffu, ef, j + 2);
            float e3 = __shfl_sync(0xffffffffu, ef, j + 3);
            uint2 u0 = hrow[s0 * 32 + lane];
            uint2 u1 = hrow[s1 * 32 + lane];
            uint2 u2 = hrow[s2 * 32 + lane];
            uint2 u3 = hrow[s3 * 32 + lane];
            float2 a0 = __half22float2(*(__half2*)&u0.x), b0 = __half22float2(*(__half2*)&u0.y);
            float2 a1 = __half22float2(*(__half2*)&u1.x), b1 = __half22float2(*(__half2*)&u1.y);
            float2 a2 = __half22float2(*(__half2*)&u2.x), b2 = __half22float2(*(__half2*)&u2.y);
            float2 a3 = __half22float2(*(__half2*)&u3.x), b3 = __half22float2(*(__half2*)&u3.y);
            ax += e0 * a0.x + e1 * a1.x + e2 * a2.x + e3 * a3.x;
            ay += e0 * a0.y + e1 * a1.y + e2 * a2.y + e3 * a3.y;
            az += e0 * b0.x + e1 * b1.x + e2 * b2.x + e3 * b3.x;
            aw += e0 * b0.y + e1 * b1.y + e2 * b2.y + e3 * b3.y;
            z += e0 + e1 + e2 + e3;
        }
        for (; j < cnt; j++) {
            int s = __shfl_sync(0xffffffffu, idx, j);
            float e = __shfl_sync(0xffffffffu, ef, j);
            uint2 u = hrow[s * 32 + lane];
            float2 f0 = __half22float2(*(__half2*)&u.x);
            float2 f1 = __half22float2(*(__half2*)&u.y);
            ax += e * f0.x;
            ay += e * f0.y;
            az += e * f1.x;
            aw += e * f1.y;
            z += e;
        }
    }
    float inv = 1.f / z;
    float4 b4 = *(const float4*)&bias[lane * 4];
    float c0 = ax * inv + b4.x;
    float c1 = ay * inv + b4.y;
    float c2 = az * inv + b4.z;
    float c3 = aw * inv + b4.w;
    if (MODE == 1) {
        c0 = fmaxf(c0, 0.f); c1 = fmaxf(c1, 0.f);
        c2 = fmaxf(c2, 0.f); c3 = fmaxf(c3, 0.f);
    }
    float tot = c0 + c1 + c2 + c3;
#pragma unroll
    for (int o = 16; o > 0; o >>= 1) tot += __shfl_xor_sync(0xffffffffu, tot, o);
    float mu = tot * (1.f / DH);
    float d0 = c0 - mu, d1 = c1 - mu, d2 = c2 - mu, d3 = c3 - mu;
    float ssq = d0 * d0 + d1 * d1 + d2 * d2 + d3 * d3;
#pragma unroll
    for (int o = 16; o > 0; o >>= 1) ssq += __shfl_xor_sync(0xffffffffu, ssq, o);
    float var = ssq * (1.f / DH);
    float sc = rsqrtf(var + EPSF);
    float4 g4 = *(const float4*)&lng[lane * 4];
    float4 bb = *(const float4*)&lnb[lane * 4];
    float o0 = d0 * sc * g4.x + bb.x;
    float o1 = d1 * sc * g4.y + bb.y;
    float o2 = d2 * sc * g4.z + bb.z;
    float o3 = d3 * sc * g4.w + bb.w;
    if (MODE == 2) {
        o0 = fmaxf(o0, 0.f); o1 = fmaxf(o1, 0.f);
        o2 = fmaxf(o2, 0.f); o3 = fmaxf(o3, 0.f);
    }
    *(float4*)&g_x2[w * DH + lane * 4] = make_float4(o0, o1, o2, o3);
}

// ---------------- fused bounds + pool + fc ----------------
__global__ void __launch_bounds__(512) k_poolfc(const void* batch,
                                                const float* __restrict__ fcW,
                                                const float* __restrict__ fcb) {
    __shared__ float part[4][DH];
    __shared__ float pr[DH];
    __shared__ int sbound[2];
    int g = blockIdx.x;
    int t = threadIdx.x;
    if (t < 2) {
        int is64 = g_is64;
        int target = g + t;
        int lo = 0, hi = NN;
        while (lo < hi) {
            int m = (lo + hi) >> 1;
            if (idx_at(batch, m, is64) < target) lo = m + 1;
            else hi = m;
        }
        sbound[t] = lo;
    }
    __syncthreads();
    int s = sbound[0], e = sbound[1];
    int c = t & 127;
    int q = t >> 7;
    int cnt = e - s;
    int chunk = (cnt + 3) >> 2;
    int rs = s + q * chunk;
    int re = min(rs + chunk, e);
    float sum = 0.f;
    for (int r = rs; r < re; r++) sum += g_x2[r * DH + c];
    part[q][c] = sum;
    __syncthreads();
    if (q == 0) {
        float tot2 = part[0][c] + part[1][c] + part[2][c] + part[3][c];
        pr[c] = tot2 / (float)max(cnt, 1);
    }
    __syncthreads();
    if (t < 128) {
        float acc = fcb[t];
#pragma unroll 4
        for (int k = 0; k < DH; k++) acc += pr[k] * fcW[k * DH + t];
        g_logits[g * DH + t] = acc;
    }
}

__global__ void k_bn(const float* __restrict__ bng, const float* __restrict__ bnb,
                     float* __restrict__ out) {
    int o = threadIdx.x;
    float mu = 0.f;
    for (int g = 0; g < GG; g++) mu += g_logits[g * DH + o];
    mu *= (1.f / GG);
    float var = 0.f;
    for (int g = 0; g < GG; g++) {
        float d = g_logits[g * DH + o] - mu;
        var += d * d;
    }
    var *= (1.f / GG);
    float sc = rsqrtf(var + EPSF);
    float gg = bng[o], bb = bnb[o];
    for (int g = 0; g < GG; g++)
        out[g * DH + o] = (g_logits[g * DH + o] - mu) * sc * gg + bb;
}

// ---------------- launch ----------------
extern "C" void kernel_launch(void* const* d_in, const int* in_sizes, int n_in,
                              void* d_out, int out_size) {
    const float* x    = (const float*)d_in[0];
    const void*  ei   = d_in[1];
    const void*  bat  = d_in[2];
    const float* W1   = (const float*)d_in[3];
    const float* as1  = (const float*)d_in[4];
    const float* ad1  = (const float*)d_in[5];
    const float* b1   = (const float*)d_in[6];
    const float* W2   = (const float*)d_in[7];
    const float* as2  = (const float*)d_in[8];
    const float* ad2  = (const float*)d_in[9];
    const float* b2   = (const float*)d_in[10];
    const float* ln1g = (const float*)d_in[11];
    const float* ln1b = (const float*)d_in[12];
    const float* ln2g = (const float*)d_in[13];
    const float* ln2b = (const float*)d_in[14];
    const float* fcW  = (const float*)d_in[15];
    const float* fcb  = (const float*)d_in[16];
    const float* bng  = (const float*)d_in[17];
    const float* bnb  = (const float*)d_in[18];
    float* out = (float*)d_out;
    int E = in_sizes[1] / 2;

    cudaFuncSetAttribute(k_hmma, cudaFuncAttributeMaxDynamicSharedMemorySize, HMMA_SMEM);

    // reordered: hmma1 is the 4th launch (profiled next round); CSR build after
    k_zero<<<98, 512>>>();
    k_wprep<<<128, 256>>>(W1, W2);
    k_detect<<<1, 256>>>((const int*)ei);
    k_hmma<<<TILES, 256, HMMA_SMEM>>>(x, 0, as1, ad1);

    k_hist<<<1024, 256>>>(ei, E);
    k_scan_bsum<<<SCAN_NB, SCAN_B>>>();
    k_scan_top<<<1, 256>>>();
    k_scan_expand<<<SCAN_NB, SCAN_B>>>();
    k_scatter<<<1024, 256>>>(ei, E);

    k_agg<1><<<NN / 8, 256>>>(b1, ln1g, ln1b);

    k_hmma<<<TILES, 256, HMMA_SMEM>>>(nullptr, 1, as2, ad2);
    k_agg<2><<<NN / 8, 256>>>(b2, ln2g, ln2b);

    k_poolfc<<<GG, 512>>>(bat, fcW, fcb);
    k_bn<<<1, 128>>>(bng, bnb, out);
}